// round 14
// baseline (speedup 1.0000x reference)
#include <cuda_runtime.h>
#include <cstdint>
#include <float.h>

#define N_NODES 50000
#define E_RAW   800000
#define E_TOT   850000   // E_RAW + N_NODES self loops
#define H1      15
#define F1      120      // H1*8
#define DIN     128
#define F2      32

#define FULL 0xFFFFFFFFu
#define NSCAN_BLK 98     // ceil(N_NODES / 512)

// ---------------- scratch (device globals; no allocation allowed) ----------------
__device__ int      g_src[(size_t)E_TOT];
__device__ int      g_dst[(size_t)E_TOT];
__device__ int      g_cnt[(size_t)N_NODES];
__device__ int      g_cursor[(size_t)N_NODES];
__device__ int      g_rowstart[(size_t)N_NODES + 1];
__device__ int      g_csr_src[(size_t)E_TOT];
__device__ int      g_part[128];
__device__ int      g_partoff[128];
__device__ unsigned g_is64;                            // edge dtype flag
__device__ unsigned g_W1big[2][DIN][F1];               // tf32 hi part of W1l/W1r
__device__ unsigned g_W1res[2][DIN][F1];               // tf32 residual part
__device__ float    g_xl1[(size_t)N_NODES * F1];
__device__ float    g_xr1[(size_t)N_NODES * F1];
__device__ float    g_hl2[(size_t)N_NODES * F2];
__device__ float    g_hr2[(size_t)N_NODES * F2];

__device__ __forceinline__ float lrelu(float v) { return v > 0.f ? v : 0.2f * v; }

__device__ __forceinline__ unsigned f2tf32(float f) {
    unsigned r;
    asm("cvt.rna.tf32.f32 %0, %1;" : "=r"(r) : "f"(f));
    return r;
}

#define MMA_TF32(c, a0, a1, a2, a3, b0, b1)                                 \
    asm volatile("mma.sync.aligned.m16n8k8.row.col.f32.tf32.tf32.f32 "      \
                 "{%0,%1,%2,%3}, {%4,%5,%6,%7}, {%8,%9}, {%0,%1,%2,%3};"    \
                 : "+f"(c[0]), "+f"(c[1]), "+f"(c[2]), "+f"(c[3])           \
                 : "r"(a0), "r"(a1), "r"(a2), "r"(a3), "r"(b0), "r"(b1))

// ---------------- edge dtype detection (sampled; 1 block) ----------------
__global__ void k_detect(const int* __restrict__ ei_raw) {
    unsigned acc = 0;
    for (int i = threadIdx.x; i < 4096; i += 256)
        acc |= (unsigned)ei_raw[2 * i + 1];
#pragma unroll
    for (int o = 16; o; o >>= 1) acc |= __shfl_xor_sync(FULL, acc, o);
    if ((threadIdx.x & 31) == 0 && acc) atomicOr(&g_is64, 1u);
}

// ---------------- init ----------------
__global__ void k_init() {
    int i = blockIdx.x * blockDim.x + threadIdx.x;
    if (i == 0) g_is64 = 0u;
    if (i < N_NODES) { g_cnt[i] = 0; g_cursor[i] = 0; }
}

// ---------------- split W1 into tf32 hi + residual (once per call) ----------------
__global__ void k_splitW(const float* __restrict__ W1l, const float* __restrict__ W1r) {
    int i = blockIdx.x * 256 + threadIdx.x;
    if (i >= 2 * DIN * F1) return;
    int mat = i / (DIN * F1), r = i % (DIN * F1);
    float f = (mat ? W1r : W1l)[r];
    unsigned big = f2tf32(f);
    float res = f - __uint_as_float(big);
    (&g_W1big[0][0][0])[(size_t)mat * DIN * F1 + r] = big;
    (&g_W1res[0][0][0])[(size_t)mat * DIN * F1 + r] = f2tf32(res);
}

// ---------------- normalize edges (2 per thread, vectorized) + self loops + count ----------------
__global__ void k_convert_count(const int* __restrict__ ei_raw) {
    int t = blockIdx.x * blockDim.x + threadIdx.x;
    int e0 = t * 2;
    if (e0 >= E_TOT) return;

    int s0, d0, s1, d1;
    bool two = (e0 + 1 < E_TOT);

    if (e0 >= E_RAW) {                 // both are self loops
        s0 = d0 = e0 - E_RAW;
        s1 = d1 = e0 + 1 - E_RAW;
    } else if (e0 + 1 == E_RAW || !two) {   // boundary straddle: scalar path
        if (g_is64) {
            s0 = ei_raw[e0]; d0 = ei_raw[E_RAW + e0];
        } else {
            s0 = ei_raw[2 * e0]; d0 = ei_raw[2 * (E_RAW + e0)];
        }
        s1 = d1 = 0;
        if (two) { s1 = d1 = e0 + 1 - E_RAW; }
    } else if (g_is64) {               // int32 data
        int2 sv = *(const int2*)(ei_raw + e0);
        int2 dv = *(const int2*)(ei_raw + E_RAW + e0);
        s0 = sv.x; s1 = sv.y; d0 = dv.x; d1 = dv.y;
    } else {                           // int64 data: low words at 2*idx (e0 even -> aligned)
        int4 sv = *(const int4*)(ei_raw + 2 * e0);
        int4 dv = *(const int4*)(ei_raw + 2 * (E_RAW + e0));
        s0 = sv.x; s1 = sv.z; d0 = dv.x; d1 = dv.z;
    }

    *(int2*)(g_src + e0) = make_int2(s0, s1);
    *(int2*)(g_dst + e0) = make_int2(d0, d1);
    atomicAdd(&g_cnt[d0], 1);
    if (two) atomicAdd(&g_cnt[d1], 1);
}

// ---------------- parallel scan: pass A (block partial sums) ----------------
__global__ void k_scan_a() {
    int idx = blockIdx.x * 512 + threadIdx.x;
    int v = (idx < N_NODES) ? g_cnt[idx] : 0;
#pragma unroll
    for (int o = 16; o; o >>= 1) v += __shfl_down_sync(FULL, v, o);
    __shared__ int ws[16];
    if ((threadIdx.x & 31) == 0) ws[threadIdx.x >> 5] = v;
    __syncthreads();
    if (threadIdx.x < 16) {
        int s = ws[threadIdx.x];
#pragma unroll
        for (int o = 8; o; o >>= 1) s += __shfl_down_sync(0xFFFFu, s, o);
        if (threadIdx.x == 0) g_part[blockIdx.x] = s;
    }
}

// ---------------- parallel scan: pass B (scan 98 partials; 1 block x 128) ----------------
__global__ void k_scan_b() {
    int t = threadIdx.x;                       // 128 threads
    int v = (t < NSCAN_BLK) ? g_part[t] : 0;
    int lane = t & 31, wid = t >> 5;
    int inc = v;
#pragma unroll
    for (int o = 1; o < 32; o <<= 1) {
        int u = __shfl_up_sync(FULL, inc, o);
        if (lane >= o) inc += u;
    }
    __shared__ int ws[4];
    if (lane == 31) ws[wid] = inc;
    __syncthreads();
    int woff = 0;
    for (int i = 0; i < wid; i++) woff += ws[i];
    g_partoff[t] = inc - v + woff;             // exclusive
    if (t == 0) g_rowstart[N_NODES] = E_TOT;
}

// ---------------- parallel scan: pass C (block exclusive scan + offset) ----------------
__global__ void k_scan_c() {
    int idx = blockIdx.x * 512 + threadIdx.x;
    int v = (idx < N_NODES) ? g_cnt[idx] : 0;
    int lane = threadIdx.x & 31, wid = threadIdx.x >> 5;
    int inc = v;
#pragma unroll
    for (int o = 1; o < 32; o <<= 1) {
        int u = __shfl_up_sync(FULL, inc, o);
        if (lane >= o) inc += u;
    }
    __shared__ int ws[16];
    if (lane == 31) ws[wid] = inc;
    __syncthreads();
    if (threadIdx.x < 16) {
        int s = ws[threadIdx.x];
#pragma unroll
        for (int o = 1; o < 16; o <<= 1) {
            int u = __shfl_up_sync(0xFFFFu, s, o);
            if (threadIdx.x >= o) s += u;
        }
        ws[threadIdx.x] = s;
    }
    __syncthreads();
    int woff = wid ? ws[wid - 1] : 0;
    if (idx < N_NODES)
        g_rowstart[idx] = inc - v + woff + g_partoff[blockIdx.x];
}

// ---------------- fill CSR (src ids grouped by dst) ----------------
__global__ void k_fill() {
    int e = blockIdx.x * blockDim.x + threadIdx.x;
    if (e >= E_TOT) return;
    int dst = g_dst[e];
    int pos = g_rowstart[dst] + atomicAdd(&g_cursor[dst], 1);
    g_csr_src[pos] = g_src[e];
}

// ---------------- GEMM1 via tensor cores: 3xTF32 mma.sync m16n8k8 ----------------
// Block = 64 nodes, 8 warps. Warps 0-3 -> Wl tiles, warps 4-7 -> Wr tiles.
// Each warp: 16 nodes x 120 cols, K=128 (16 k-tiles x 15 n-tiles x 3 mma).
__global__ void k_gemm1_mma(const float* __restrict__ x) {
    __shared__ float sx[64 * 132];              // 64 nodes x 128 floats, stride 132 (pad)
    int tid = threadIdx.x;
    int nb0 = blockIdx.x * 64;

    for (int i = tid; i < 64 * 32; i += 256) {
        int n = i >> 5, q = i & 31;
        float4 v = make_float4(0, 0, 0, 0);
        if (nb0 + n < N_NODES)
            v = *((const float4*)(x + (size_t)(nb0 + n) * DIN) + q);
        *(float4*)(sx + n * 132 + q * 4) = v;
    }
    __syncthreads();

    int w = tid >> 5, lane = tid & 31;
    int mat = w >> 2;                           // 0 = Wl, 1 = Wr
    int m0 = (w & 3) * 16;                      // local node tile base
    int nbase = nb0 + m0;
    if (nbase >= N_NODES) return;               // N % 16 == 0 -> surviving warps full

    int g = lane >> 2, t = lane & 3;            // groupID, threadID_in_group
    const unsigned* Wb = &g_W1big[mat][0][0];
    const unsigned* Wr_ = &g_W1res[mat][0][0];
    float* outp = mat ? g_xr1 : g_xl1;

    float C[15][4];
#pragma unroll
    for (int nt = 0; nt < 15; nt++)
#pragma unroll
        for (int c = 0; c < 4; c++) C[nt][c] = 0.f;

    for (int kt = 0; kt < 16; kt++) {
        // A fragment (16x8 tf32): a0:(g,t) a1:(g+8,t) a2:(g,t+4) a3:(g+8,t+4)
        float f0 = sx[(m0 + g) * 132 + kt * 8 + t];
        float f1 = sx[(m0 + g + 8) * 132 + kt * 8 + t];
        float f2 = sx[(m0 + g) * 132 + kt * 8 + t + 4];
        float f3 = sx[(m0 + g + 8) * 132 + kt * 8 + t + 4];
        unsigned ab0 = f2tf32(f0), ab1 = f2tf32(f1), ab2 = f2tf32(f2), ab3 = f2tf32(f3);
        unsigned ar0 = f2tf32(f0 - __uint_as_float(ab0));
        unsigned ar1 = f2tf32(f1 - __uint_as_float(ab1));
        unsigned ar2 = f2tf32(f2 - __uint_as_float(ab2));
        unsigned ar3 = f2tf32(f3 - __uint_as_float(ab3));

        int krow0 = (kt * 8 + t) * F1;
        int krow1 = (kt * 8 + t + 4) * F1;
#pragma unroll
        for (int nt = 0; nt < 15; nt++) {
            // B fragment (8x8): b0:(row t, col g) b1:(row t+4, col g)
            unsigned bb0 = __ldg(&Wb[krow0 + nt * 8 + g]);
            unsigned bb1 = __ldg(&Wb[krow1 + nt * 8 + g]);
            unsigned br0 = __ldg(&Wr_[krow0 + nt * 8 + g]);
            unsigned br1 = __ldg(&Wr_[krow1 + nt * 8 + g]);
            MMA_TF32(C[nt], ab0, ab1, ab2, ab3, bb0, bb1);   // hi*hi
            MMA_TF32(C[nt], ab0, ab1, ab2, ab3, br0, br1);   // hi*lo
            MMA_TF32(C[nt], ar0, ar1, ar2, ar3, bb0, bb1);   // lo*hi
        }
    }

    // C fragment: c0:(g,2t) c1:(g,2t+1) c2:(g+8,2t) c3:(g+8,2t+1)
#pragma unroll
    for (int nt = 0; nt < 15; nt++) {
        *(float2*)(outp + (size_t)(nbase + g) * F1 + nt * 8 + 2 * t) =
            make_float2(C[nt][0], C[nt][1]);
        *(float2*)(outp + (size_t)(nbase + g + 8) * F1 + nt * 8 + 2 * t) =
            make_float2(C[nt][2], C[nt][3]);
    }
}

// ---------------- FUSED layer1 aggregate + GEMM2 (block = 32 dst nodes, 8 warps) ----------------
__global__ void k_agg1gemm2(const float* __restrict__ att, const float* __restrict__ b1,
                            const float* __restrict__ Wl, const float* __restrict__ Wr) {
    __shared__ float4 sx[32 * 30];              // 32 nodes x 120 floats = 15.4KB
    int tid = threadIdx.x;
    int w = tid >> 5, lane = tid & 31;
    int nb0 = blockIdx.x * 32;
    int g = lane < 30 ? lane : 0;

    // ---- phase 1: aggregate 4 dst nodes per warp ----
    float4 at = __ldg((const float4*)att + g);
    float4 bv = __ldg((const float4*)b1 + g);

    for (int q = 0; q < 4; q++) {
        int l = w * 4 + q;                      // local node 0..31
        int dst = nb0 + l;
        if (dst >= N_NODES) break;

        float4 b = *((const float4*)(g_xr1 + (size_t)dst * F1) + g);
        int s0 = g_rowstart[dst], s1 = g_rowstart[dst + 1];

        float4 acc = make_float4(0, 0, 0, 0);
        float den = 0.f;

#define EDGE1(A)                                                                  \
    {                                                                             \
        float p = lrelu(A.x + b.x) * at.x + lrelu(A.y + b.y) * at.y +             \
                  lrelu(A.z + b.z) * at.z + lrelu(A.w + b.w) * at.w;              \
        float p2 = __shfl_down_sync(FULL, p, 1);                                  \
        float ee = __expf(p + p2);                                                \
        float ww = __shfl_sync(FULL, ee, lane & 30);                              \
        acc.x += ww * A.x; acc.y += ww * A.y; acc.z += ww * A.z; acc.w += ww * A.w; \
        if ((lane & 1) == 0) den += ee;                                           \
    }

        int i = s0;
        for (; i + 3 < s1; i += 4) {
            int sa = g_csr_src[i], sb = g_csr_src[i + 1];
            int sc = g_csr_src[i + 2], sd = g_csr_src[i + 3];
            float4 a0 = __ldg((const float4*)(g_xl1 + (size_t)sa * F1) + g);
            float4 a1 = __ldg((const float4*)(g_xl1 + (size_t)sb * F1) + g);
            float4 a2 = __ldg((const float4*)(g_xl1 + (size_t)sc * F1) + g);
            float4 a3 = __ldg((const float4*)(g_xl1 + (size_t)sd * F1) + g);
            EDGE1(a0) EDGE1(a1) EDGE1(a2) EDGE1(a3)
        }
        for (; i < s1; i++) {
            int sa = g_csr_src[i];
            float4 a0 = __ldg((const float4*)(g_xl1 + (size_t)sa * F1) + g);
            EDGE1(a0)
        }
#undef EDGE1

        float d = __shfl_sync(FULL, den, lane & 30);
        if (lane < 30) {
            float inv = 1.f / d;
            float4 v;
            v.x = acc.x * inv + bv.x; v.y = acc.y * inv + bv.y;
            v.z = acc.z * inv + bv.z; v.w = acc.w * inv + bv.w;
            v.x = v.x > 0.f ? v.x : __expf(v.x) - 1.f;
            v.y = v.y > 0.f ? v.y : __expf(v.y) - 1.f;
            v.z = v.z > 0.f ? v.z : __expf(v.z) - 1.f;
            v.w = v.w > 0.f ? v.w : __expf(v.w) - 1.f;
            sx[l * 30 + lane] = v;
        }
    }
    __syncthreads();

    // ---- phase 2: GEMM2 on the smem tile ----
    int mat = w & 1;
    int l0 = (w >> 1) * 8;
    int nb = nb0 + l0;
    if (nb >= N_NODES) return;

    const float* W = mat ? Wr : Wl;             // [F1, F2] row-major, lane = col
    float* outp = mat ? g_hr2 : g_hl2;

    float acc2[8] = {0, 0, 0, 0, 0, 0, 0, 0};
    for (int kq = 0; kq < 30; kq++) {
        float w0 = __ldg(&W[(size_t)(kq * 4 + 0) * F2 + lane]);
        float w1 = __ldg(&W[(size_t)(kq * 4 + 1) * F2 + lane]);
        float w2 = __ldg(&W[(size_t)(kq * 4 + 2) * F2 + lane]);
        float w3 = __ldg(&W[(size_t)(kq * 4 + 3) * F2 + lane]);
#pragma unroll
        for (int j = 0; j < 8; j++) {
            float4 xj = sx[(l0 + j) * 30 + kq];
            acc2[j] += xj.x * w0 + xj.y * w1 + xj.z * w2 + xj.w * w3;
        }
    }
#pragma unroll
    for (int j = 0; j < 8; j++)
        outp[(size_t)(nb + j) * F2 + lane] = acc2[j];
}

// ---------------- layer2 aggregate + bias + log_softmax: warp per dst, 4-wide ----------------
__global__ void k_agg2(const float* __restrict__ att2, const float* __restrict__ b2,
                       float* __restrict__ out) {
    int dst = (blockIdx.x * blockDim.x + threadIdx.x) >> 5;
    int lane = threadIdx.x & 31;
    if (dst >= N_NODES) return;

    float b = g_hr2[(size_t)dst * F2 + lane];
    float at = __ldg(&att2[lane]);
    int s0 = g_rowstart[dst], s1 = g_rowstart[dst + 1];

    float acc = 0.f, den = 0.f;

#define EDGE2(A)                                                    \
    {                                                               \
        float t = lrelu(A + b) * at;                                \
        _Pragma("unroll")                                           \
        for (int o = 16; o; o >>= 1) t += __shfl_xor_sync(FULL, t, o); \
        float w = __expf(t);                                        \
        den += w;                                                   \
        acc += w * A;                                               \
    }

    int i = s0;
    for (; i + 3 < s1; i += 4) {
        int sa = g_csr_src[i], sb = g_csr_src[i + 1];
        int sc = g_csr_src[i + 2], sd = g_csr_src[i + 3];
        float a0 = g_hl2[(size_t)sa * F2 + lane];
        float a1 = g_hl2[(size_t)sb * F2 + lane];
        float a2 = g_hl2[(size_t)sc * F2 + lane];
        float a3 = g_hl2[(size_t)sd * F2 + lane];
        EDGE2(a0) EDGE2(a1) EDGE2(a2) EDGE2(a3)
    }
    for (; i < s1; i++) {
        int sa = g_csr_src[i];
        float a0 = g_hl2[(size_t)sa * F2 + lane];
        EDGE2(a0)
    }
#undef EDGE2

    float v = acc / den + __ldg(&b2[lane]);
    float m = v;
#pragma unroll
    for (int o = 16; o; o >>= 1) m = fmaxf(m, __shfl_xor_sync(FULL, m, o));
    float ex = expf(v - m);
    float s = ex;
#pragma unroll
    for (int o = 16; o; o >>= 1) s += __shfl_xor_sync(FULL, s, o);
    float ls = v - m - logf(s);
    out[(size_t)dst * F2 + lane] = v;
    out[(size_t)N_NODES * F2 + (size_t)dst * F2 + lane] = ls;
}

// ---------------- launcher (two-stream: CSR build overlaps GEMM1) ----------------
extern "C" void kernel_launch(void* const* d_in, const int* in_sizes, int n_in,
                              void* d_out, int out_size) {
    const float* x    = (const float*)d_in[0];
    const int*   ei   = (const int*)d_in[1];     // dtype detected at runtime
    const float* W1l  = (const float*)d_in[2];
    const float* W1r  = (const float*)d_in[3];
    const float* att1 = (const float*)d_in[4];
    const float* b1   = (const float*)d_in[5];
    const float* W2l  = (const float*)d_in[6];
    const float* W2r  = (const float*)d_in[7];
    const float* att2 = (const float*)d_in[8];
    const float* b2   = (const float*)d_in[9];
    float* out = (float*)d_out;

    static cudaStream_t s_side = nullptr;
    static cudaEvent_t  s_fork = nullptr, s_join = nullptr;
    if (!s_side) {
        cudaStreamCreateWithFlags(&s_side, cudaStreamNonBlocking);
        cudaEventCreateWithFlags(&s_fork, cudaEventDisableTiming);
        cudaEventCreateWithFlags(&s_join, cudaEventDisableTiming);
    }

    // fork: CSR build on side stream, W-split + GEMM1 on main (default) stream
    cudaEventRecord(s_fork, 0);
    cudaStreamWaitEvent(s_side, s_fork, 0);

    k_init<<<(N_NODES + 255) / 256, 256, 0, s_side>>>();
    k_detect<<<1, 256, 0, s_side>>>(ei);
    k_convert_count<<<((E_TOT + 1) / 2 + 255) / 256, 256, 0, s_side>>>(ei);
    k_scan_a<<<NSCAN_BLK, 512, 0, s_side>>>();
    k_scan_b<<<1, 128, 0, s_side>>>();
    k_scan_c<<<NSCAN_BLK, 512, 0, s_side>>>();
    k_fill<<<(E_TOT + 255) / 256, 256, 0, s_side>>>();
    cudaEventRecord(s_join, s_side);

    k_splitW<<<(2 * DIN * F1 + 255) / 256, 256>>>(W1l, W1r);
    k_gemm1_mma<<<(N_NODES + 63) / 64, 256>>>(x);

    // join: fused agg1+gemm2 needs both GEMM1 output and the CSR
    cudaStreamWaitEvent(0, s_join, 0);
    k_agg1gemm2<<<(N_NODES + 31) / 32, 256>>>(att1, b1, W2l, W2r);
    k_agg2<<<(N_NODES * 32 + 255) / 256, 256>>>(att2, b2, out);
}

// round 15
// speedup vs baseline: 1.0460x; 1.0460x over previous
#include <cuda_runtime.h>
#include <cstdint>
#include <float.h>

#define N_NODES 50000
#define E_RAW   800000
#define E_TOT   850000   // E_RAW + N_NODES self loops
#define H1      15
#define F1      120      // H1*8
#define DIN     128
#define F2      32

#define FULL 0xFFFFFFFFu
#define NSCAN_BLK 98     // ceil(N_NODES / 512)

// ---------------- scratch (device globals; no allocation allowed) ----------------
__device__ int      g_src[(size_t)E_TOT];
__device__ int      g_dst[(size_t)E_TOT];
__device__ int      g_cnt[(size_t)N_NODES];
__device__ int      g_cursor[(size_t)N_NODES];
__device__ int      g_rowstart[(size_t)N_NODES + 1];
__device__ int      g_csr_src[(size_t)E_TOT];
__device__ int      g_part[128];
__device__ int      g_partoff[128];
__device__ unsigned g_is64;                            // edge dtype flag
__device__ float    g_xl1[(size_t)N_NODES * F1];
__device__ float    g_xr1[(size_t)N_NODES * F1];
__device__ float    g_hl2[(size_t)N_NODES * F2];
__device__ float    g_hr2[(size_t)N_NODES * F2];

__device__ __forceinline__ float lrelu(float v) { return v > 0.f ? v : 0.2f * v; }

// ---------------- edge dtype detection (sampled; 1 block) ----------------
__global__ void k_detect(const int* __restrict__ ei_raw) {
    unsigned acc = 0;
    for (int i = threadIdx.x; i < 4096; i += 256)
        acc |= (unsigned)ei_raw[2 * i + 1];
#pragma unroll
    for (int o = 16; o; o >>= 1) acc |= __shfl_xor_sync(FULL, acc, o);
    if ((threadIdx.x & 31) == 0 && acc) atomicOr(&g_is64, 1u);
}

// ---------------- init ----------------
__global__ void k_init() {
    int i = blockIdx.x * blockDim.x + threadIdx.x;
    if (i == 0) g_is64 = 0u;
    if (i < N_NODES) { g_cnt[i] = 0; g_cursor[i] = 0; }
}

// ---------------- normalize edges (2 per thread, vectorized) + self loops + count ----------------
__global__ void k_convert_count(const int* __restrict__ ei_raw) {
    int t = blockIdx.x * blockDim.x + threadIdx.x;
    int e0 = t * 2;
    if (e0 >= E_TOT) return;

    int s0, d0, s1, d1;
    bool two = (e0 + 1 < E_TOT);

    if (e0 >= E_RAW) {                 // both are self loops
        s0 = d0 = e0 - E_RAW;
        s1 = d1 = e0 + 1 - E_RAW;
    } else if (e0 + 1 == E_RAW || !two) {   // boundary straddle: scalar path
        if (g_is64) {
            s0 = ei_raw[e0]; d0 = ei_raw[E_RAW + e0];
        } else {
            s0 = ei_raw[2 * e0]; d0 = ei_raw[2 * (E_RAW + e0)];
        }
        s1 = d1 = 0;
        if (two) { s1 = d1 = e0 + 1 - E_RAW; }
    } else if (g_is64) {               // int32 data
        int2 sv = *(const int2*)(ei_raw + e0);
        int2 dv = *(const int2*)(ei_raw + E_RAW + e0);
        s0 = sv.x; s1 = sv.y; d0 = dv.x; d1 = dv.y;
    } else {                           // int64 data: low words at 2*idx (e0 even -> aligned)
        int4 sv = *(const int4*)(ei_raw + 2 * e0);
        int4 dv = *(const int4*)(ei_raw + 2 * (E_RAW + e0));
        s0 = sv.x; s1 = sv.z; d0 = dv.x; d1 = dv.z;
    }

    *(int2*)(g_src + e0) = make_int2(s0, s1);
    *(int2*)(g_dst + e0) = make_int2(d0, d1);
    atomicAdd(&g_cnt[d0], 1);
    if (two) atomicAdd(&g_cnt[d1], 1);
}

// ---------------- parallel scan: pass A (block partial sums) ----------------
__global__ void k_scan_a() {
    int idx = blockIdx.x * 512 + threadIdx.x;
    int v = (idx < N_NODES) ? g_cnt[idx] : 0;
#pragma unroll
    for (int o = 16; o; o >>= 1) v += __shfl_down_sync(FULL, v, o);
    __shared__ int ws[16];
    if ((threadIdx.x & 31) == 0) ws[threadIdx.x >> 5] = v;
    __syncthreads();
    if (threadIdx.x < 16) {
        int s = ws[threadIdx.x];
#pragma unroll
        for (int o = 8; o; o >>= 1) s += __shfl_down_sync(0xFFFFu, s, o);
        if (threadIdx.x == 0) g_part[blockIdx.x] = s;
    }
}

// ---------------- parallel scan: pass B (scan 98 partials; 1 block x 128) ----------------
__global__ void k_scan_b() {
    int t = threadIdx.x;                       // 128 threads
    int v = (t < NSCAN_BLK) ? g_part[t] : 0;
    int lane = t & 31, wid = t >> 5;
    int inc = v;
#pragma unroll
    for (int o = 1; o < 32; o <<= 1) {
        int u = __shfl_up_sync(FULL, inc, o);
        if (lane >= o) inc += u;
    }
    __shared__ int ws[4];
    if (lane == 31) ws[wid] = inc;
    __syncthreads();
    int woff = 0;
    for (int i = 0; i < wid; i++) woff += ws[i];
    g_partoff[t] = inc - v + woff;             // exclusive
    if (t == 0) g_rowstart[N_NODES] = E_TOT;
}

// ---------------- parallel scan: pass C (block exclusive scan + offset) ----------------
__global__ void k_scan_c() {
    int idx = blockIdx.x * 512 + threadIdx.x;
    int v = (idx < N_NODES) ? g_cnt[idx] : 0;
    int lane = threadIdx.x & 31, wid = threadIdx.x >> 5;
    int inc = v;
#pragma unroll
    for (int o = 1; o < 32; o <<= 1) {
        int u = __shfl_up_sync(FULL, inc, o);
        if (lane >= o) inc += u;
    }
    __shared__ int ws[16];
    if (lane == 31) ws[wid] = inc;
    __syncthreads();
    if (threadIdx.x < 16) {
        int s = ws[threadIdx.x];
#pragma unroll
        for (int o = 1; o < 16; o <<= 1) {
            int u = __shfl_up_sync(0xFFFFu, s, o);
            if (threadIdx.x >= o) s += u;
        }
        ws[threadIdx.x] = s;
    }
    __syncthreads();
    int woff = wid ? ws[wid - 1] : 0;
    if (idx < N_NODES)
        g_rowstart[idx] = inc - v + woff + g_partoff[blockIdx.x];
}

// ---------------- fill CSR (src ids grouped by dst) ----------------
__global__ void k_fill() {
    int e = blockIdx.x * blockDim.x + threadIdx.x;
    if (e >= E_TOT) return;
    int dst = g_dst[e];
    int pos = g_rowstart[dst] + atomicAdd(&g_cursor[dst], 1);
    g_csr_src[pos] = g_src[e];
}

// ---------------- GEMM1: smem x-tile, warp = 8 nodes x ONE matrix ----------------
__global__ void k_gemm1(const float* __restrict__ x,
                        const float* __restrict__ Wl,
                        const float* __restrict__ Wr) {
    __shared__ float4 sx[32 * 32];              // 32 nodes x 128 floats = 16KB
    int tid = threadIdx.x;
    int nb0 = blockIdx.x * 32;

    const float4* x4 = (const float4*)x + (size_t)nb0 * 32;
    for (int i = tid; i < 32 * 32; i += 256)
        if (nb0 + (i >> 5) < N_NODES) sx[i] = x4[i];
    __syncthreads();

    int w = tid >> 5, lane = tid & 31;
    int mat = w & 1;
    int l0 = (w >> 1) * 8;
    int nb = nb0 + l0;
    if (nb >= N_NODES) return;                  // N % 8 == 0 -> whole group valid

    const float4* w4 = (const float4*)(mat ? Wr : Wl);   // row k -> k*30 + g
    float* outp = mat ? g_xr1 : g_xl1;
    int g = lane < 30 ? lane : 0;               // lanes 30,31 compute garbage, never store

    float4 acc[8];
#pragma unroll
    for (int j = 0; j < 8; j++) acc[j] = make_float4(0, 0, 0, 0);

    for (int kq = 0; kq < 32; kq++) {
        float4 w0 = __ldg(&w4[(size_t)(kq * 4 + 0) * 30 + g]);
        float4 w1 = __ldg(&w4[(size_t)(kq * 4 + 1) * 30 + g]);
        float4 w2 = __ldg(&w4[(size_t)(kq * 4 + 2) * 30 + g]);
        float4 w3 = __ldg(&w4[(size_t)(kq * 4 + 3) * 30 + g]);
#pragma unroll
        for (int j = 0; j < 8; j++) {
            float4 xj = sx[(l0 + j) * 32 + kq];   // broadcast LDS.128
            acc[j].x += xj.x * w0.x + xj.y * w1.x + xj.z * w2.x + xj.w * w3.x;
            acc[j].y += xj.x * w0.y + xj.y * w1.y + xj.z * w2.y + xj.w * w3.y;
            acc[j].z += xj.x * w0.z + xj.y * w1.z + xj.z * w2.z + xj.w * w3.z;
            acc[j].w += xj.x * w0.w + xj.y * w1.w + xj.z * w2.w + xj.w * w3.w;
        }
    }
    if (lane < 30) {
#pragma unroll
        for (int j = 0; j < 8; j++)
            *(float4*)(outp + (size_t)(nb + j) * F1 + lane * 4) = acc[j];
    }
}

// ---------------- FUSED layer1 aggregate + GEMM2 (block = 32 dst nodes, 8 warps) ----------------
// Phase 1: warp w aggregates dst nodes nb0+4w..nb0+4w+3 (CSR, 8-wide pipelined),
//          applies /den + bias + ELU, writes h rows into the smem tile.
// Phase 2: warp = 8 nodes x ONE matrix (lane = output col) reads tile -> hl2/hr2.
__global__ void k_agg1gemm2(const float* __restrict__ att, const float* __restrict__ b1,
                            const float* __restrict__ Wl, const float* __restrict__ Wr) {
    __shared__ float4 sx[32 * 30];              // 32 nodes x 120 floats = 15.4KB
    int tid = threadIdx.x;
    int w = tid >> 5, lane = tid & 31;
    int nb0 = blockIdx.x * 32;
    int g = lane < 30 ? lane : 0;

    // ---- phase 1: aggregate 4 dst nodes per warp, 8-wide edge pipeline ----
    float4 at = __ldg((const float4*)att + g);
    float4 bv = __ldg((const float4*)b1 + g);

    for (int q = 0; q < 4; q++) {
        int l = w * 4 + q;                      // local node 0..31
        int dst = nb0 + l;
        if (dst >= N_NODES) break;

        float4 b = *((const float4*)(g_xr1 + (size_t)dst * F1) + g);
        int s0 = g_rowstart[dst], s1 = g_rowstart[dst + 1];

        float4 acc = make_float4(0, 0, 0, 0);
        float den = 0.f;

#define EDGE1(A)                                                                  \
    {                                                                             \
        float p = lrelu(A.x + b.x) * at.x + lrelu(A.y + b.y) * at.y +             \
                  lrelu(A.z + b.z) * at.z + lrelu(A.w + b.w) * at.w;              \
        float p2 = __shfl_down_sync(FULL, p, 1);                                  \
        float ee = __expf(p + p2);                                                \
        float ww = __shfl_sync(FULL, ee, lane & 30);                              \
        acc.x += ww * A.x; acc.y += ww * A.y; acc.z += ww * A.z; acc.w += ww * A.w; \
        if ((lane & 1) == 0) den += ee;                                           \
    }

        int i = s0;
        for (; i + 7 < s1; i += 8) {
            int se[8];
#pragma unroll
            for (int u = 0; u < 8; u++) se[u] = g_csr_src[i + u];
            float4 a0 = __ldg((const float4*)(g_xl1 + (size_t)se[0] * F1) + g);
            float4 a1 = __ldg((const float4*)(g_xl1 + (size_t)se[1] * F1) + g);
            float4 a2 = __ldg((const float4*)(g_xl1 + (size_t)se[2] * F1) + g);
            float4 a3 = __ldg((const float4*)(g_xl1 + (size_t)se[3] * F1) + g);
            float4 a4 = __ldg((const float4*)(g_xl1 + (size_t)se[4] * F1) + g);
            float4 a5 = __ldg((const float4*)(g_xl1 + (size_t)se[5] * F1) + g);
            float4 a6 = __ldg((const float4*)(g_xl1 + (size_t)se[6] * F1) + g);
            float4 a7 = __ldg((const float4*)(g_xl1 + (size_t)se[7] * F1) + g);
            EDGE1(a0) EDGE1(a1) EDGE1(a2) EDGE1(a3)
            EDGE1(a4) EDGE1(a5) EDGE1(a6) EDGE1(a7)
        }
        for (; i + 3 < s1; i += 4) {
            int sa = g_csr_src[i], sb = g_csr_src[i + 1];
            int sc = g_csr_src[i + 2], sd = g_csr_src[i + 3];
            float4 a0 = __ldg((const float4*)(g_xl1 + (size_t)sa * F1) + g);
            float4 a1 = __ldg((const float4*)(g_xl1 + (size_t)sb * F1) + g);
            float4 a2 = __ldg((const float4*)(g_xl1 + (size_t)sc * F1) + g);
            float4 a3 = __ldg((const float4*)(g_xl1 + (size_t)sd * F1) + g);
            EDGE1(a0) EDGE1(a1) EDGE1(a2) EDGE1(a3)
        }
        for (; i < s1; i++) {
            int sa = g_csr_src[i];
            float4 a0 = __ldg((const float4*)(g_xl1 + (size_t)sa * F1) + g);
            EDGE1(a0)
        }
#undef EDGE1

        float d = __shfl_sync(FULL, den, lane & 30);
        if (lane < 30) {
            float inv = 1.f / d;
            float4 v;
            v.x = acc.x * inv + bv.x; v.y = acc.y * inv + bv.y;
            v.z = acc.z * inv + bv.z; v.w = acc.w * inv + bv.w;
            v.x = v.x > 0.f ? v.x : __expf(v.x) - 1.f;
            v.y = v.y > 0.f ? v.y : __expf(v.y) - 1.f;
            v.z = v.z > 0.f ? v.z : __expf(v.z) - 1.f;
            v.w = v.w > 0.f ? v.w : __expf(v.w) - 1.f;
            sx[l * 30 + lane] = v;
        }
    }
    __syncthreads();

    // ---- phase 2: GEMM2 on the smem tile ----
    int mat = w & 1;
    int l0 = (w >> 1) * 8;
    int nb = nb0 + l0;
    if (nb >= N_NODES) return;

    const float* W = mat ? Wr : Wl;             // [F1, F2] row-major, lane = col
    float* outp = mat ? g_hr2 : g_hl2;

    float acc2[8] = {0, 0, 0, 0, 0, 0, 0, 0};
    for (int kq = 0; kq < 30; kq++) {
        float w0 = __ldg(&W[(size_t)(kq * 4 + 0) * F2 + lane]);
        float w1 = __ldg(&W[(size_t)(kq * 4 + 1) * F2 + lane]);
        float w2 = __ldg(&W[(size_t)(kq * 4 + 2) * F2 + lane]);
        float w3 = __ldg(&W[(size_t)(kq * 4 + 3) * F2 + lane]);
#pragma unroll
        for (int j = 0; j < 8; j++) {
            float4 xj = sx[(l0 + j) * 30 + kq];
            acc2[j] += xj.x * w0 + xj.y * w1 + xj.z * w2 + xj.w * w3;
        }
    }
#pragma unroll
    for (int j = 0; j < 8; j++)
        outp[(size_t)(nb + j) * F2 + lane] = acc2[j];
}

// ---------------- layer2 aggregate + bias + log_softmax: warp per dst, 8-wide ----------------
__global__ void k_agg2(const float* __restrict__ att2, const float* __restrict__ b2,
                       float* __restrict__ out) {
    int dst = (blockIdx.x * blockDim.x + threadIdx.x) >> 5;
    int lane = threadIdx.x & 31;
    if (dst >= N_NODES) return;

    float b = g_hr2[(size_t)dst * F2 + lane];
    float at = __ldg(&att2[lane]);
    int s0 = g_rowstart[dst], s1 = g_rowstart[dst + 1];

    float acc = 0.f, den = 0.f;

#define EDGE2(A)                                                    \
    {                                                               \
        float t = lrelu(A + b) * at;                                \
        _Pragma("unroll")                                           \
        for (int o = 16; o; o >>= 1) t += __shfl_xor_sync(FULL, t, o); \
        float w = __expf(t);                                        \
        den += w;                                                   \
        acc += w * A;                                               \
    }

    int i = s0;
    for (; i + 7 < s1; i += 8) {
        int se[8];
#pragma unroll
        for (int u = 0; u < 8; u++) se[u] = g_csr_src[i + u];
        float a0 = g_hl2[(size_t)se[0] * F2 + lane];
        float a1 = g_hl2[(size_t)se[1] * F2 + lane];
        float a2 = g_hl2[(size_t)se[2] * F2 + lane];
        float a3 = g_hl2[(size_t)se[3] * F2 + lane];
        float a4 = g_hl2[(size_t)se[4] * F2 + lane];
        float a5 = g_hl2[(size_t)se[5] * F2 + lane];
        float a6 = g_hl2[(size_t)se[6] * F2 + lane];
        float a7 = g_hl2[(size_t)se[7] * F2 + lane];
        EDGE2(a0) EDGE2(a1) EDGE2(a2) EDGE2(a3)
        EDGE2(a4) EDGE2(a5) EDGE2(a6) EDGE2(a7)
    }
    for (; i + 3 < s1; i += 4) {
        int sa = g_csr_src[i], sb = g_csr_src[i + 1];
        int sc = g_csr_src[i + 2], sd = g_csr_src[i + 3];
        float a0 = g_hl2[(size_t)sa * F2 + lane];
        float a1 = g_hl2[(size_t)sb * F2 + lane];
        float a2 = g_hl2[(size_t)sc * F2 + lane];
        float a3 = g_hl2[(size_t)sd * F2 + lane];
        EDGE2(a0) EDGE2(a1) EDGE2(a2) EDGE2(a3)
    }
    for (; i < s1; i++) {
        int sa = g_csr_src[i];
        float a0 = g_hl2[(size_t)sa * F2 + lane];
        EDGE2(a0)
    }
#undef EDGE2

    float v = acc / den + __ldg(&b2[lane]);
    float m = v;
#pragma unroll
    for (int o = 16; o; o >>= 1) m = fmaxf(m, __shfl_xor_sync(FULL, m, o));
    float ex = expf(v - m);
    float s = ex;
#pragma unroll
    for (int o = 16; o; o >>= 1) s += __shfl_xor_sync(FULL, s, o);
    float ls = v - m - logf(s);
    out[(size_t)dst * F2 + lane] = v;
    out[(size_t)N_NODES * F2 + (size_t)dst * F2 + lane] = ls;
}

// ---------------- launcher (two-stream: CSR build overlaps GEMM1) ----------------
extern "C" void kernel_launch(void* const* d_in, const int* in_sizes, int n_in,
                              void* d_out, int out_size) {
    const float* x    = (const float*)d_in[0];
    const int*   ei   = (const int*)d_in[1];     // dtype detected at runtime
    const float* W1l  = (const float*)d_in[2];
    const float* W1r  = (const float*)d_in[3];
    const float* att1 = (const float*)d_in[4];
    const float* b1   = (const float*)d_in[5];
    const float* W2l  = (const float*)d_in[6];
    const float* W2r  = (const float*)d_in[7];
    const float* att2 = (const float*)d_in[8];
    const float* b2   = (const float*)d_in[9];
    float* out = (float*)d_out;

    static cudaStream_t s_side = nullptr;
    static cudaEvent_t  s_fork = nullptr, s_join = nullptr;
    if (!s_side) {
        cudaStreamCreateWithFlags(&s_side, cudaStreamNonBlocking);
        cudaEventCreateWithFlags(&s_fork, cudaEventDisableTiming);
        cudaEventCreateWithFlags(&s_join, cudaEventDisableTiming);
    }

    int gblocks = (N_NODES + 31) / 32;           // 1563

    // fork: CSR build on side stream, GEMM1 on main (default) stream
    cudaEventRecord(s_fork, 0);
    cudaStreamWaitEvent(s_side, s_fork, 0);

    k_init<<<(N_NODES + 255) / 256, 256, 0, s_side>>>();
    k_detect<<<1, 256, 0, s_side>>>(ei);
    k_convert_count<<<((E_TOT + 1) / 2 + 255) / 256, 256, 0, s_side>>>(ei);
    k_scan_a<<<NSCAN_BLK, 512, 0, s_side>>>();
    k_scan_b<<<1, 128, 0, s_side>>>();
    k_scan_c<<<NSCAN_BLK, 512, 0, s_side>>>();
    k_fill<<<(E_TOT + 255) / 256, 256, 0, s_side>>>();
    cudaEventRecord(s_join, s_side);

    k_gemm1<<<gblocks, 256>>>(x, W1l, W1r);

    // join: fused agg1+gemm2 needs both GEMM1 output and the CSR
    cudaStreamWaitEvent(0, s_join, 0);
    k_agg1gemm2<<<gblocks, 256>>>(att1, b1, W2l, W2r);
    k_agg2<<<(N_NODES * 32 + 255) / 256, 256>>>(att2, b2, out);
}

// round 16
// speedup vs baseline: 1.0865x; 1.0386x over previous
#include <cuda_runtime.h>
#include <cstdint>
#include <float.h>

#define N_NODES 50000
#define E_RAW   800000
#define E_TOT   850000   // E_RAW + N_NODES self loops
#define H1      15
#define F1      120      // H1*8
#define DIN     128
#define F2      32

#define FULL 0xFFFFFFFFu
#define NSCAN_BLK 98     // ceil(N_NODES / 512)

// ---------------- scratch (device globals; no allocation allowed) ----------------
__device__ int      g_src[(size_t)E_TOT];
__device__ int      g_dst[(size_t)E_TOT];
__device__ int      g_cnt[(size_t)N_NODES];
__device__ int      g_cursor[(size_t)N_NODES];
__device__ int      g_rowstart[(size_t)N_NODES + 1];
__device__ int      g_csr_src[(size_t)E_TOT];
__device__ int      g_part[128];
__device__ int      g_partoff[128];
__device__ unsigned g_is64;                            // edge dtype flag
__device__ float    g_xl1[(size_t)N_NODES * F1];
__device__ float    g_xr1[(size_t)N_NODES * F1];
__device__ float    g_hl2[(size_t)N_NODES * F2];
__device__ float    g_hr2[(size_t)N_NODES * F2];

__device__ __forceinline__ float lrelu(float v) { return v > 0.f ? v : 0.2f * v; }

// ---------------- edge dtype detection (sampled; 1 block) ----------------
__global__ void k_detect(const int* __restrict__ ei_raw) {
    unsigned acc = 0;
    for (int i = threadIdx.x; i < 4096; i += 256)
        acc |= (unsigned)ei_raw[2 * i + 1];
#pragma unroll
    for (int o = 16; o; o >>= 1) acc |= __shfl_xor_sync(FULL, acc, o);
    if ((threadIdx.x & 31) == 0 && acc) atomicOr(&g_is64, 1u);
}

// ---------------- init ----------------
__global__ void k_init() {
    int i = blockIdx.x * blockDim.x + threadIdx.x;
    if (i == 0) g_is64 = 0u;
    if (i < N_NODES) { g_cnt[i] = 0; g_cursor[i] = 0; }
}

// ---------------- normalize edges (2 per thread, vectorized) + self loops + count ----------------
__global__ void k_convert_count(const int* __restrict__ ei_raw) {
    int t = blockIdx.x * blockDim.x + threadIdx.x;
    int e0 = t * 2;
    if (e0 >= E_TOT) return;

    int s0, d0, s1, d1;
    bool two = (e0 + 1 < E_TOT);

    if (e0 >= E_RAW) {                 // both are self loops
        s0 = d0 = e0 - E_RAW;
        s1 = d1 = e0 + 1 - E_RAW;
    } else if (e0 + 1 == E_RAW || !two) {   // boundary straddle: scalar path
        if (g_is64) {
            s0 = ei_raw[e0]; d0 = ei_raw[E_RAW + e0];
        } else {
            s0 = ei_raw[2 * e0]; d0 = ei_raw[2 * (E_RAW + e0)];
        }
        s1 = d1 = 0;
        if (two) { s1 = d1 = e0 + 1 - E_RAW; }
    } else if (g_is64) {               // int32 data
        int2 sv = *(const int2*)(ei_raw + e0);
        int2 dv = *(const int2*)(ei_raw + E_RAW + e0);
        s0 = sv.x; s1 = sv.y; d0 = dv.x; d1 = dv.y;
    } else {                           // int64 data: low words at 2*idx (e0 even -> aligned)
        int4 sv = *(const int4*)(ei_raw + 2 * e0);
        int4 dv = *(const int4*)(ei_raw + 2 * (E_RAW + e0));
        s0 = sv.x; s1 = sv.z; d0 = dv.x; d1 = dv.z;
    }

    *(int2*)(g_src + e0) = make_int2(s0, s1);
    *(int2*)(g_dst + e0) = make_int2(d0, d1);
    atomicAdd(&g_cnt[d0], 1);
    if (two) atomicAdd(&g_cnt[d1], 1);
}

// ---------------- parallel scan: pass A (block partial sums) ----------------
__global__ void k_scan_a() {
    int idx = blockIdx.x * 512 + threadIdx.x;
    int v = (idx < N_NODES) ? g_cnt[idx] : 0;
#pragma unroll
    for (int o = 16; o; o >>= 1) v += __shfl_down_sync(FULL, v, o);
    __shared__ int ws[16];
    if ((threadIdx.x & 31) == 0) ws[threadIdx.x >> 5] = v;
    __syncthreads();
    if (threadIdx.x < 16) {
        int s = ws[threadIdx.x];
#pragma unroll
        for (int o = 8; o; o >>= 1) s += __shfl_down_sync(0xFFFFu, s, o);
        if (threadIdx.x == 0) g_part[blockIdx.x] = s;
    }
}

// ---------------- parallel scan: pass B (scan 98 partials; 1 block x 128) ----------------
__global__ void k_scan_b() {
    int t = threadIdx.x;                       // 128 threads
    int v = (t < NSCAN_BLK) ? g_part[t] : 0;
    int lane = t & 31, wid = t >> 5;
    int inc = v;
#pragma unroll
    for (int o = 1; o < 32; o <<= 1) {
        int u = __shfl_up_sync(FULL, inc, o);
        if (lane >= o) inc += u;
    }
    __shared__ int ws[4];
    if (lane == 31) ws[wid] = inc;
    __syncthreads();
    int woff = 0;
    for (int i = 0; i < wid; i++) woff += ws[i];
    g_partoff[t] = inc - v + woff;             // exclusive
    if (t == 0) g_rowstart[N_NODES] = E_TOT;
}

// ---------------- parallel scan: pass C (block exclusive scan + offset) ----------------
__global__ void k_scan_c() {
    int idx = blockIdx.x * 512 + threadIdx.x;
    int v = (idx < N_NODES) ? g_cnt[idx] : 0;
    int lane = threadIdx.x & 31, wid = threadIdx.x >> 5;
    int inc = v;
#pragma unroll
    for (int o = 1; o < 32; o <<= 1) {
        int u = __shfl_up_sync(FULL, inc, o);
        if (lane >= o) inc += u;
    }
    __shared__ int ws[16];
    if (lane == 31) ws[wid] = inc;
    __syncthreads();
    if (threadIdx.x < 16) {
        int s = ws[threadIdx.x];
#pragma unroll
        for (int o = 1; o < 16; o <<= 1) {
            int u = __shfl_up_sync(0xFFFFu, s, o);
            if (threadIdx.x >= o) s += u;
        }
        ws[threadIdx.x] = s;
    }
    __syncthreads();
    int woff = wid ? ws[wid - 1] : 0;
    if (idx < N_NODES)
        g_rowstart[idx] = inc - v + woff + g_partoff[blockIdx.x];
}

// ---------------- fill CSR (src ids grouped by dst) ----------------
__global__ void k_fill() {
    int e = blockIdx.x * blockDim.x + threadIdx.x;
    if (e >= E_TOT) return;
    int dst = g_dst[e];
    int pos = g_rowstart[dst] + atomicAdd(&g_cursor[dst], 1);
    g_csr_src[pos] = g_src[e];
}

// ---------------- GEMM1: smem x-tile, warp = 8 nodes x ONE matrix ----------------
__global__ void k_gemm1(const float* __restrict__ x,
                        const float* __restrict__ Wl,
                        const float* __restrict__ Wr) {
    __shared__ float4 sx[32 * 32];              // 32 nodes x 128 floats = 16KB
    int tid = threadIdx.x;
    int nb0 = blockIdx.x * 32;

    const float4* x4 = (const float4*)x + (size_t)nb0 * 32;
    for (int i = tid; i < 32 * 32; i += 256)
        if (nb0 + (i >> 5) < N_NODES) sx[i] = x4[i];
    __syncthreads();

    int w = tid >> 5, lane = tid & 31;
    int mat = w & 1;
    int l0 = (w >> 1) * 8;
    int nb = nb0 + l0;
    if (nb >= N_NODES) return;                  // N % 8 == 0 -> whole group valid

    const float4* w4 = (const float4*)(mat ? Wr : Wl);   // row k -> k*30 + g
    float* outp = mat ? g_xr1 : g_xl1;
    int g = lane < 30 ? lane : 0;               // lanes 30,31 compute garbage, never store

    float4 acc[8];
#pragma unroll
    for (int j = 0; j < 8; j++) acc[j] = make_float4(0, 0, 0, 0);

    for (int kq = 0; kq < 32; kq++) {
        float4 w0 = __ldg(&w4[(size_t)(kq * 4 + 0) * 30 + g]);
        float4 w1 = __ldg(&w4[(size_t)(kq * 4 + 1) * 30 + g]);
        float4 w2 = __ldg(&w4[(size_t)(kq * 4 + 2) * 30 + g]);
        float4 w3 = __ldg(&w4[(size_t)(kq * 4 + 3) * 30 + g]);
#pragma unroll
        for (int j = 0; j < 8; j++) {
            float4 xj = sx[(l0 + j) * 32 + kq];   // broadcast LDS.128
            acc[j].x += xj.x * w0.x + xj.y * w1.x + xj.z * w2.x + xj.w * w3.x;
            acc[j].y += xj.x * w0.y + xj.y * w1.y + xj.z * w2.y + xj.w * w3.y;
            acc[j].z += xj.x * w0.z + xj.y * w1.z + xj.z * w2.z + xj.w * w3.z;
            acc[j].w += xj.x * w0.w + xj.y * w1.w + xj.z * w2.w + xj.w * w3.w;
        }
    }
    if (lane < 30) {
#pragma unroll
        for (int j = 0; j < 8; j++)
            *(float4*)(outp + (size_t)(nb + j) * F1 + lane * 4) = acc[j];
    }
}

// ---------------- FUSED layer1 aggregate + GEMM2 (block = 32 dst nodes, 8 warps) ----------------
// Phase 1: warp w aggregates dst nodes nb0+4w..nb0+4w+3 (CSR, 4-wide pipelined),
//          applies /den + bias + ELU, writes h rows into the smem tile.
// Phase 2: warp = 8 nodes x ONE matrix (lane = output col) reads tile -> hl2/hr2.
__global__ void k_agg1gemm2(const float* __restrict__ att, const float* __restrict__ b1,
                            const float* __restrict__ Wl, const float* __restrict__ Wr) {
    __shared__ float4 sx[32 * 30];              // 32 nodes x 120 floats = 15.4KB
    int tid = threadIdx.x;
    int w = tid >> 5, lane = tid & 31;
    int nb0 = blockIdx.x * 32;
    int g = lane < 30 ? lane : 0;

    // ---- phase 1: aggregate 4 dst nodes per warp ----
    float4 at = __ldg((const float4*)att + g);
    float4 bv = __ldg((const float4*)b1 + g);

    for (int q = 0; q < 4; q++) {
        int l = w * 4 + q;                      // local node 0..31
        int dst = nb0 + l;
        if (dst >= N_NODES) break;

        float4 b = *((const float4*)(g_xr1 + (size_t)dst * F1) + g);
        int s0 = g_rowstart[dst], s1 = g_rowstart[dst + 1];

        float4 acc = make_float4(0, 0, 0, 0);
        float den = 0.f;

#define EDGE1(A)                                                                  \
    {                                                                             \
        float p = lrelu(A.x + b.x) * at.x + lrelu(A.y + b.y) * at.y +             \
                  lrelu(A.z + b.z) * at.z + lrelu(A.w + b.w) * at.w;              \
        float p2 = __shfl_down_sync(FULL, p, 1);                                  \
        float ee = __expf(p + p2);                                                \
        float ww = __shfl_sync(FULL, ee, lane & 30);                              \
        acc.x += ww * A.x; acc.y += ww * A.y; acc.z += ww * A.z; acc.w += ww * A.w; \
        if ((lane & 1) == 0) den += ee;                                           \
    }

        int i = s0;
        for (; i + 3 < s1; i += 4) {
            int sa = g_csr_src[i], sb = g_csr_src[i + 1];
            int sc = g_csr_src[i + 2], sd = g_csr_src[i + 3];
            float4 a0 = __ldg((const float4*)(g_xl1 + (size_t)sa * F1) + g);
            float4 a1 = __ldg((const float4*)(g_xl1 + (size_t)sb * F1) + g);
            float4 a2 = __ldg((const float4*)(g_xl1 + (size_t)sc * F1) + g);
            float4 a3 = __ldg((const float4*)(g_xl1 + (size_t)sd * F1) + g);
            EDGE1(a0) EDGE1(a1) EDGE1(a2) EDGE1(a3)
        }
        for (; i < s1; i++) {
            int sa = g_csr_src[i];
            float4 a0 = __ldg((const float4*)(g_xl1 + (size_t)sa * F1) + g);
            EDGE1(a0)
        }
#undef EDGE1

        float d = __shfl_sync(FULL, den, lane & 30);
        if (lane < 30) {
            float inv = 1.f / d;
            float4 v;
            v.x = acc.x * inv + bv.x; v.y = acc.y * inv + bv.y;
            v.z = acc.z * inv + bv.z; v.w = acc.w * inv + bv.w;
            v.x = v.x > 0.f ? v.x : __expf(v.x) - 1.f;
            v.y = v.y > 0.f ? v.y : __expf(v.y) - 1.f;
            v.z = v.z > 0.f ? v.z : __expf(v.z) - 1.f;
            v.w = v.w > 0.f ? v.w : __expf(v.w) - 1.f;
            sx[l * 30 + lane] = v;
        }
    }
    __syncthreads();

    // ---- phase 2: GEMM2 on the smem tile ----
    int mat = w & 1;
    int l0 = (w >> 1) * 8;
    int nb = nb0 + l0;
    if (nb >= N_NODES) return;

    const float* W = mat ? Wr : Wl;             // [F1, F2] row-major, lane = col
    float* outp = mat ? g_hr2 : g_hl2;

    float acc2[8] = {0, 0, 0, 0, 0, 0, 0, 0};
    for (int kq = 0; kq < 30; kq++) {
        float w0 = __ldg(&W[(size_t)(kq * 4 + 0) * F2 + lane]);
        float w1 = __ldg(&W[(size_t)(kq * 4 + 1) * F2 + lane]);
        float w2 = __ldg(&W[(size_t)(kq * 4 + 2) * F2 + lane]);
        float w3 = __ldg(&W[(size_t)(kq * 4 + 3) * F2 + lane]);
#pragma unroll
        for (int j = 0; j < 8; j++) {
            float4 xj = sx[(l0 + j) * 30 + kq];
            acc2[j] += xj.x * w0 + xj.y * w1 + xj.z * w2 + xj.w * w3;
        }
    }
#pragma unroll
    for (int j = 0; j < 8; j++)
        outp[(size_t)(nb + j) * F2 + lane] = acc2[j];
}

// ---------------- layer2 aggregate + bias + log_softmax: 4 dst per warp, 8 lanes each ----------------
__global__ void k_agg2(const float* __restrict__ att2, const float* __restrict__ b2,
                       float* __restrict__ out) {
    int warp = (blockIdx.x * blockDim.x + threadIdx.x) >> 5;
    int lane = threadIdx.x & 31;
    int grp = lane >> 3, q = lane & 7;          // group = local node, q = lane in group
    int dst = warp * 4 + grp;
    bool valid = (dst < N_NODES);
    int dstc = valid ? dst : N_NODES - 1;

    float4 b = *((const float4*)(g_hr2 + (size_t)dstc * F2) + q);
    float4 at = __ldg((const float4*)att2 + q);
    float4 bv = __ldg((const float4*)b2 + q);

    int s0 = g_rowstart[dstc], s1 = g_rowstart[dstc + 1];
    int deg = s1 - s0;                          // >= 1 (self loop)

    // warp-max degree so all lanes stay converged
    int nmax = deg;
    nmax = max(nmax, __shfl_xor_sync(FULL, nmax, 8));
    nmax = max(nmax, __shfl_xor_sync(FULL, nmax, 16));

    float4 acc = make_float4(0, 0, 0, 0);
    float den = 0.f;

    for (int i = 0; i < nmax; i++) {
        int idx = s0 + min(i, deg - 1);         // clamped in-range
        int src = g_csr_src[idx];
        float4 a = *((const float4*)(g_hl2 + (size_t)src * F2) + q);
        float t = lrelu(a.x + b.x) * at.x + lrelu(a.y + b.y) * at.y +
                  lrelu(a.z + b.z) * at.z + lrelu(a.w + b.w) * at.w;
        t += __shfl_xor_sync(FULL, t, 4);
        t += __shfl_xor_sync(FULL, t, 2);
        t += __shfl_xor_sync(FULL, t, 1);
        float ww = __expf(t);
        if (i < deg) {
            den += ww;
            acc.x += ww * a.x; acc.y += ww * a.y;
            acc.z += ww * a.z; acc.w += ww * a.w;
        }
    }

    float inv = 1.f / den;
    float4 v;
    v.x = acc.x * inv + bv.x; v.y = acc.y * inv + bv.y;
    v.z = acc.z * inv + bv.z; v.w = acc.w * inv + bv.w;

    // log_softmax over the node's 32 values (4 local + 3-shfl tree in 8-lane group)
    float m = fmaxf(fmaxf(v.x, v.y), fmaxf(v.z, v.w));
    m = fmaxf(m, __shfl_xor_sync(FULL, m, 4));
    m = fmaxf(m, __shfl_xor_sync(FULL, m, 2));
    m = fmaxf(m, __shfl_xor_sync(FULL, m, 1));
    float s = expf(v.x - m) + expf(v.y - m) + expf(v.z - m) + expf(v.w - m);
    s += __shfl_xor_sync(FULL, s, 4);
    s += __shfl_xor_sync(FULL, s, 2);
    s += __shfl_xor_sync(FULL, s, 1);
    float ls = m + logf(s);

    if (valid) {
        *((float4*)(out + (size_t)dst * F2) + q) = v;
        float4 lv = make_float4(v.x - ls, v.y - ls, v.z - ls, v.w - ls);
        *((float4*)(out + (size_t)N_NODES * F2 + (size_t)dst * F2) + q) = lv;
    }
}

// ---------------- launcher (two-stream: CSR build overlaps GEMM1) ----------------
extern "C" void kernel_launch(void* const* d_in, const int* in_sizes, int n_in,
                              void* d_out, int out_size) {
    const float* x    = (const float*)d_in[0];
    const int*   ei   = (const int*)d_in[1];     // dtype detected at runtime
    const float* W1l  = (const float*)d_in[2];
    const float* W1r  = (const float*)d_in[3];
    const float* att1 = (const float*)d_in[4];
    const float* b1   = (const float*)d_in[5];
    const float* W2l  = (const float*)d_in[6];
    const float* W2r  = (const float*)d_in[7];
    const float* att2 = (const float*)d_in[8];
    const float* b2   = (const float*)d_in[9];
    float* out = (float*)d_out;

    static cudaStream_t s_side = nullptr;
    static cudaEvent_t  s_fork = nullptr, s_join = nullptr;
    if (!s_side) {
        cudaStreamCreateWithFlags(&s_side, cudaStreamNonBlocking);
        cudaEventCreateWithFlags(&s_fork, cudaEventDisableTiming);
        cudaEventCreateWithFlags(&s_join, cudaEventDisableTiming);
    }

    int gblocks = (N_NODES + 31) / 32;           // 1563

    // fork: CSR build on side stream, GEMM1 on main (default) stream
    cudaEventRecord(s_fork, 0);
    cudaStreamWaitEvent(s_side, s_fork, 0);

    k_init<<<(N_NODES + 255) / 256, 256, 0, s_side>>>();
    k_detect<<<1, 256, 0, s_side>>>(ei);
    k_convert_count<<<((E_TOT + 1) / 2 + 255) / 256, 256, 0, s_side>>>(ei);
    k_scan_a<<<NSCAN_BLK, 512, 0, s_side>>>();
    k_scan_b<<<1, 128, 0, s_side>>>();
    k_scan_c<<<NSCAN_BLK, 512, 0, s_side>>>();
    k_fill<<<(E_TOT + 255) / 256, 256, 0, s_side>>>();
    cudaEventRecord(s_join, s_side);

    k_gemm1<<<gblocks, 256>>>(x, W1l, W1r);

    // join: fused agg1+gemm2 needs both GEMM1 output and the CSR
    cudaStreamWaitEvent(0, s_join, 0);
    k_agg1gemm2<<<gblocks, 256>>>(att1, b1, W2l, W2r);
    k_agg2<<<((N_NODES + 3) / 4 * 32 + 255) / 256, 256>>>(att2, b2, out);
}